// round 11
// baseline (speedup 1.0000x reference)
#include <cuda_runtime.h>
#include <cuda_fp16.h>
#include <cstdint>

// VQ-VAE on GB300: fp16 3-term split mma.sync distances, FMNMX top-1 +
// slice-2nd tripwire (R10, 235.9us), with B operands pre-packed in MMA
// fragment order so the inner loop uses 8x LDS.128 instead of 32x LDS.32.
//
// d_out layout (fp32): [0]=loss, [1..1+N*D)=quantized, [1+N*D]=perplexity,
//                      [2+N*D ..)=encodings one-hot.

#define N_INPUTS 131072
#define EMB_DIM  64
#define NUM_EMB  1024
#define M_TILE   128
#define THREADS  256
#define PHASES   8
#define PHASE_CODES 128
#define MARGIN   0.01f

#define Q_OFF   ((size_t)1)
#define PP_OFF  ((size_t)(1 + (size_t)N_INPUTS * EMB_DIM))
#define ENC_OFF ((size_t)(2 + (size_t)N_INPUTS * EMB_DIM))

// smem layout (bytes from dynamic-smem base)
// Fragment-ordered E tile: 128 codes x 128B per split, parity-swizzled.
#define ESPLIT      (PHASE_CODES * 128)         // 16384
#define EBUF_SIZE   (2 * ESPLIT)                // e1 + e2 = 32768
#define SM_E        0                           // 2 buffers = 65536
#define SM_NORM     65536                       // 1024 floats
#define SM_CANDV    69632                       // 128*4 floats (slice top-1)
#define SM_CAND2    71680                       // 128*4 floats (slice 2nd val)
#define SM_CANDI    73728                       // 128*4 ints
#define SM_BIDX     75776                       // 128 ints
#define SM_RED      76288                       // 8 doubles
#define SM_QN       76352                       // int
#define SM_QROWS    76356                       // 128 ints
#define SM_XSTG     76880                       // 8 warps * 256B
#define DYN_SMEM    78976

__device__ float  g_enorm[NUM_EMB];
// Fragment-ordered packed embeddings: per code, 32 unsigneds (=128B):
//   index = code*32 + tig*8 + q,  q = ks*2 + r,
//   value = half2( e[16ks + 2tig + 8r], e[16ks + 2tig + 8r + 1] )
__device__ __half g_e1[NUM_EMB * EMB_DIM];
__device__ __half g_e2[NUM_EMB * EMB_DIM];
__device__ int    g_count[NUM_EMB];
__device__ double g_loss;

__device__ __forceinline__ uint32_t s2u(const void* p) {
    uint32_t a;
    asm("{ .reg .u64 t; cvta.to.shared.u64 t, %1; cvt.u32.u64 %0, t; }"
        : "=r"(a) : "l"(p));
    return a;
}

__device__ __forceinline__ void split2(float lo, float hi,
                                       unsigned& h1, unsigned& h2) {
    __half2 a = __floats2half2_rn(lo, hi);
    float2 af = __half22float2(a);
    __half2 b = __floats2half2_rn(lo - af.x, hi - af.y);
    h1 = *reinterpret_cast<unsigned*>(&a);
    h2 = *reinterpret_cast<unsigned*>(&b);
}

#define MMA16816(C, A, b0, b1)                                                \
    asm volatile(                                                             \
        "mma.sync.aligned.m16n8k16.row.col.f32.f16.f16.f32 "                  \
        "{%0,%1,%2,%3},{%4,%5,%6,%7},{%8,%9},{%0,%1,%2,%3};"                  \
        : "+f"((C)[0]), "+f"((C)[1]), "+f"((C)[2]), "+f"((C)[3])              \
        : "r"((A)[0]), "r"((A)[1]), "r"((A)[2]), "r"((A)[3]),                 \
          "r"(b0), "r"(b1))

#define CP16(dst, src)                                                        \
    asm volatile("cp.async.ca.shared.global [%0], [%1], 16;"                  \
                 :: "r"(dst), "l"(src) : "memory")

#define STG_CS_F2(p, v)                                                       \
    asm volatile("st.global.cs.v2.f32 [%0], {%1, %2};"                        \
                 :: "l"(p), "f"((v).x), "f"((v).y) : "memory")

// top-1 + value-only 2nd, FMNMX-based (first-occurrence wins on ties:
// strict < for index update, codes visited ascending)
#define UPD(h, d, ix)                                                         \
    do {                                                                      \
        float _d = (d);                                                       \
        float _t = fmaxf(s0v[h], _d);                                         \
        s1v[h] = fminf(s1v[h], _t);                                           \
        if (_d < s0v[h]) s0i[h] = (ix);                                       \
        s0v[h] = fminf(s0v[h], _d);                                           \
    } while (0)

// ---------------------------------------------------------------------------
// Prep: norms, fp16 split of embeddings in FRAGMENT order, zero accumulators.
// Thread (k, seg): seg-th 8 dims of code k. q = seg, pairs j=0..3 map to tig.
// ---------------------------------------------------------------------------
__global__ void prep_kernel(const float* __restrict__ emb) {
    int g = blockIdx.x * blockDim.x + threadIdx.x;   // 0..8191
    int k = g >> 3, seg = g & 7;
    const float* er = emb + (size_t)k * EMB_DIM + seg * 8;
    unsigned* e1u = (unsigned*)g_e1;
    unsigned* e2u = (unsigned*)g_e2;
    float s = 0.0f;
#pragma unroll
    for (int j = 0; j < 4; j++) {        // j = tig
        float a = er[2 * j], b = er[2 * j + 1];
        s = fmaf(a, a, s);
        s = fmaf(b, b, s);
        unsigned h1, h2;
        split2(a, b, h1, h2);
        int o = k * 32 + j * 8 + seg;    // fragment-order slot
        e1u[o] = h1;
        e2u[o] = h2;
    }
#pragma unroll
    for (int o = 4; o > 0; o >>= 1)
        s += __shfl_down_sync(0xffffffffu, s, o, 8);
    if (seg == 0) {
        g_enorm[k] = s;
        g_count[k] = 0;
        if (k == 0) g_loss = 0.0;
    }
}

// ---------------------------------------------------------------------------
// Main kernel: CTA = 128 rows; warp w owns rows w*16..w*16+15.
// ---------------------------------------------------------------------------
__device__ __forceinline__ void prefetch_phase(uint32_t smu, int tid, int phase) {
    uint32_t dbase = smu + SM_E + (phase & 1) * EBUF_SIZE;
    const char* s1 = (const char*)g_e1 + (size_t)phase * PHASE_CODES * 128;
    const char* s2 = (const char*)g_e2 + (size_t)phase * PHASE_CODES * 128;
#pragma unroll
    for (int j = 0; j < 4; j++) {
        int c = tid + j * THREADS;       // 0..1023: code*8 + tig*2 + h
        int code = c >> 3, tig = (c >> 1) & 3, h = c & 1;
        // parity swizzle: odd codes shift 16B (mod 128) -> conflict-free LDS.128
        uint32_t sw = (uint32_t)((tig * 32 + h * 16 + ((code & 1) << 4)) & 127);
        uint32_t dst = dbase + code * 128 + sw;
        CP16(dst, s1 + c * 16);          // gmem is linear in chunk id
        CP16(dst + ESPLIT, s2 + c * 16);
    }
}

__global__ void __launch_bounds__(THREADS, 2)
vq_main_kernel(const float* __restrict__ inputs,
               const float* __restrict__ emb,
               float* __restrict__ out) {
    extern __shared__ char sm[];
    const uint32_t smu = s2u(sm);
    const int tid  = threadIdx.x;
    const int wid  = tid >> 5;
    const int lane = tid & 31;
    const int gid  = lane >> 2;
    const int tig  = lane & 3;
    const int row0 = blockIdx.x * M_TILE;

    if (tid == 0) *(int*)(sm + SM_QN) = 0;

    // enorm -> smem
    float* nsm = (float*)(sm + SM_NORM);
    for (int i = tid; i < NUM_EMB; i += THREADS) nsm[i] = g_enorm[i];

    // A fragments (x split), held for the whole kernel.
    unsigned X1[4][4], X2[4][4];
    {
        const float* xp  = inputs + (size_t)(row0 + wid * 16 + gid) * EMB_DIM;
        const float* xp8 = xp + 8 * EMB_DIM;
#pragma unroll
        for (int ks = 0; ks < 4; ks++) {
            int c0 = ks * 16 + 2 * tig;
            float2 v;
            v = *(const float2*)(xp  + c0);     split2(v.x, v.y, X1[ks][0], X2[ks][0]);
            v = *(const float2*)(xp8 + c0);     split2(v.x, v.y, X1[ks][1], X2[ks][1]);
            v = *(const float2*)(xp  + c0 + 8); split2(v.x, v.y, X1[ks][2], X2[ks][2]);
            v = *(const float2*)(xp8 + c0 + 8); split2(v.x, v.y, X1[ks][3], X2[ks][3]);
        }
    }

    prefetch_phase(smu, tid, 0);
    asm volatile("cp.async.commit_group;" ::: "memory");

    float s0v[2] = {3.4e38f, 3.4e38f}, s1v[2] = {3.4e38f, 3.4e38f};
    int   s0i[2] = {0, 0};

    // B-load swizzled sub-offsets (depend only on tig/gid; code parity = gid&1)
    const uint32_t par = (uint32_t)((gid & 1) << 4);
    const uint32_t sw0 = (uint32_t)((tig * 32 + par) & 127);
    const uint32_t sw1 = (uint32_t)((tig * 32 + 16 + par) & 127);

    float2* const enc = (float2*)(out + ENC_OFF);   // 8B-aligned

    for (int phase = 0; phase < PHASES; phase++) {
        if (phase + 1 < PHASES) {
            prefetch_phase(smu, tid, phase + 1);
            asm volatile("cp.async.commit_group;" ::: "memory");
            asm volatile("cp.async.wait_group 1;" ::: "memory");
        } else {
            asm volatile("cp.async.wait_group 0;" ::: "memory");
        }
        __syncthreads();

        const char* e1b = sm + SM_E + (phase & 1) * EBUF_SIZE;
        const char* e2b = e1b + ESPLIT;

        for (int it = 0; it < PHASE_CODES / 16; it++) {
            const int lc = it * 16;
            // B fragments: 2 nt x 4 ks x 2 regs, both splits, via LDS.128.
            unsigned B1[2][4][2], B2[2][4][2];
#pragma unroll
            for (int nt = 0; nt < 2; nt++) {
                const uint32_t base = (uint32_t)(lc + nt * 8 + gid) * 128;
                uint4 v0 = *(const uint4*)(e1b + base + sw0);  // ks0, ks1
                uint4 v1 = *(const uint4*)(e1b + base + sw1);  // ks2, ks3
                B1[nt][0][0] = v0.x; B1[nt][0][1] = v0.y;
                B1[nt][1][0] = v0.z; B1[nt][1][1] = v0.w;
                B1[nt][2][0] = v1.x; B1[nt][2][1] = v1.y;
                B1[nt][3][0] = v1.z; B1[nt][3][1] = v1.w;
                uint4 w0 = *(const uint4*)(e2b + base + sw0);
                uint4 w1 = *(const uint4*)(e2b + base + sw1);
                B2[nt][0][0] = w0.x; B2[nt][0][1] = w0.y;
                B2[nt][1][0] = w0.z; B2[nt][1][1] = w0.w;
                B2[nt][2][0] = w1.x; B2[nt][2][1] = w1.y;
                B2[nt][3][0] = w1.z; B2[nt][3][1] = w1.w;
            }
            float C0[4] = {0.f, 0.f, 0.f, 0.f};
            float C1[4] = {0.f, 0.f, 0.f, 0.f};
#pragma unroll
            for (int ks = 0; ks < 4; ks++) {
                MMA16816(C0, X1[ks], B1[0][ks][0], B1[0][ks][1]);
                MMA16816(C1, X1[ks], B1[1][ks][0], B1[1][ks][1]);
            }
#pragma unroll
            for (int ks = 0; ks < 4; ks++) {
                MMA16816(C0, X1[ks], B2[0][ks][0], B2[0][ks][1]);
                MMA16816(C1, X1[ks], B2[1][ks][0], B2[1][ks][1]);
            }
#pragma unroll
            for (int ks = 0; ks < 4; ks++) {
                MMA16816(C0, X2[ks], B1[0][ks][0], B1[0][ks][1]);
                MMA16816(C1, X2[ks], B1[1][ks][0], B1[1][ks][1]);
            }
            // dist + per-row-half top1 + value-only 2nd (codes ascending)
            const int cb = phase * PHASE_CODES + lc;
            float n0 = nsm[cb + 2 * tig],     n1 = nsm[cb + 2 * tig + 1];
            float n2 = nsm[cb + 8 + 2 * tig], n3 = nsm[cb + 9 + 2 * tig];
            UPD(0, fmaf(-2.f, C0[0], n0), cb + 2 * tig);
            UPD(0, fmaf(-2.f, C0[1], n1), cb + 2 * tig + 1);
            UPD(0, fmaf(-2.f, C1[0], n2), cb + 8 + 2 * tig);
            UPD(0, fmaf(-2.f, C1[1], n3), cb + 9 + 2 * tig);
            UPD(1, fmaf(-2.f, C0[2], n0), cb + 2 * tig);
            UPD(1, fmaf(-2.f, C0[3], n1), cb + 2 * tig + 1);
            UPD(1, fmaf(-2.f, C1[2], n2), cb + 8 + 2 * tig);
            UPD(1, fmaf(-2.f, C1[3], n3), cb + 9 + 2 * tig);
        }

        // ---- stream the one-hot ZERO slab for this phase's 128 columns ----
        {
            const float2 z = make_float2(0.0f, 0.0f);
#pragma unroll 4
            for (int i = tid; i < M_TILE * 64; i += THREADS) {
                int r = i >> 6, c2 = i & 63;
                float2* p = enc + (size_t)(row0 + r) * 512 + phase * 64 + c2;
                STG_CS_F2(p, z);
            }
        }
        __syncthreads();   // buffer reuse safety for next prefetch
    }

    // ---- publish candidates: row -> 4 (top1 val, idx) + 4 slice-2nd vals ----
    float* cv = (float*)(sm + SM_CANDV);
    float* c2 = (float*)(sm + SM_CAND2);
    int*   ci = (int*)(sm + SM_CANDI);
    {
        int r0 = wid * 16 + gid, r1 = r0 + 8;
        cv[r0 * 4 + tig] = s0v[0]; ci[r0 * 4 + tig] = s0i[0]; c2[r0 * 4 + tig] = s1v[0];
        cv[r1 * 4 + tig] = s0v[1]; ci[r1 * 4 + tig] = s0i[1]; c2[r1 * 4 + tig] = s1v[1];
    }
    __syncthreads();

    // ---- per-row: merge, tripwire, rerank or queue exact full scan ----
    int* s_bidx = (int*)(sm + SM_BIDX);
    int* q_n    = (int*)(sm + SM_QN);
    int* q_rows = (int*)(sm + SM_QROWS);
    if (tid < M_TILE) {
        const float* cvr = cv + tid * 4;
        const float* c2r = c2 + tid * 4;
        const int*   cir = ci + tid * 4;
        float m0 = 3.4e38f; int mi = 0x7fffffff;
#pragma unroll
        for (int s = 0; s < 4; s++) {
            float v = cvr[s]; int id = cir[s];
            if (v < m0 || (v == m0 && id < mi)) { m0 = v; mi = id; }
        }
        const float lim = m0 + MARGIN;
        float h2 = fminf(fminf(c2r[0], c2r[1]), fminf(c2r[2], c2r[3]));
        if (h2 <= lim) {
            // a hidden slice-2nd may be in-margin: exact full scan needed
            q_rows[atomicAdd(q_n, 1)] = tid;
        } else {
            int cnt = 0;
#pragma unroll
            for (int s = 0; s < 4; s++) cnt += (cvr[s] <= lim);
            int bidx = mi;
            if (cnt > 1) {               // exact fp32 rerank among published
                const float* xr = inputs + (size_t)(row0 + tid) * EMB_DIM;
                float bd = 3.4e38f; int bb = 0x7fffffff;
#pragma unroll 1
                for (int s = 0; s < 4; s++) {
                    if (cvr[s] <= lim) {
                        int id = cir[s];
                        const float4* er = (const float4*)(emb + (size_t)id * EMB_DIM);
                        float dot = 0.f;
#pragma unroll
                        for (int i = 0; i < EMB_DIM / 4; i++) {
                            float4 e = __ldg(er + i);
                            float4 x = *(const float4*)(xr + 4 * i);
                            dot = fmaf(x.x, e.x, dot); dot = fmaf(x.y, e.y, dot);
                            dot = fmaf(x.z, e.z, dot); dot = fmaf(x.w, e.w, dot);
                        }
                        float d = fmaf(-2.f, dot, nsm[id]);
                        if (d < bd || (d == bd && id < bb)) { bd = d; bb = id; }
                    }
                }
                bidx = bb;
            }
            s_bidx[tid] = bidx;
            atomicAdd(&g_count[bidx], 1);
            out[ENC_OFF + (size_t)(row0 + tid) * NUM_EMB + bidx] = 1.0f;
        }
    }
    __syncthreads();

    // ---- exact full scan for queued rows (one warp per row; rare) ----
    {
        const int nq = *q_n;
        float4* xs = (float4*)(sm + SM_XSTG + wid * 256);
        for (int qi = wid; qi < nq; qi += 8) {
            const int r = q_rows[qi];
            {
                const float2 v = *(const float2*)
                    (inputs + (size_t)(row0 + r) * EMB_DIM + 2 * lane);
                ((float2*)xs)[lane] = v;
            }
            __syncwarp();
            float bd = 3.4e38f; int bi = 0x7fffffff;
            for (int c = lane; c < NUM_EMB; c += 32) {
                const float4* er = (const float4*)(emb + (size_t)c * EMB_DIM);
                float dot = 0.f;
#pragma unroll
                for (int i = 0; i < EMB_DIM / 4; i++) {
                    float4 e = __ldg(er + i);
                    float4 x = xs[i];
                    dot = fmaf(x.x, e.x, dot); dot = fmaf(x.y, e.y, dot);
                    dot = fmaf(x.z, e.z, dot); dot = fmaf(x.w, e.w, dot);
                }
                float d = fmaf(-2.f, dot, nsm[c]);
                if (d < bd || (d == bd && c < bi)) { bd = d; bi = c; }
            }
#pragma unroll
            for (int o = 16; o > 0; o >>= 1) {
                float od = __shfl_down_sync(0xffffffffu, bd, o);
                int   oi = __shfl_down_sync(0xffffffffu, bi, o);
                if (od < bd || (od == bd && oi < bi)) { bd = od; bi = oi; }
            }
            bi = __shfl_sync(0xffffffffu, bi, 0);
            if (lane == 0) {
                s_bidx[r] = bi;
                atomicAdd(&g_count[bi], 1);
                out[ENC_OFF + (size_t)(row0 + r) * NUM_EMB + bi] = 1.0f;
            }
            __syncwarp();
        }
    }
    __syncthreads();

    // ---- quantized + commitment loss ----
    double* s_red = (double*)(sm + SM_RED);
    float ss = 0.0f;
    for (int i = tid; i < M_TILE * EMB_DIM; i += THREADS) {
        int r = i >> 6, cl = i & 63;
        float x = inputs[(size_t)(row0 + r) * EMB_DIM + cl];
        float e = emb[(size_t)s_bidx[r] * EMB_DIM + cl];
        float d = e - x;
        out[Q_OFF + (size_t)(row0 + r) * EMB_DIM + cl] = x + d;
        ss = fmaf(d, d, ss);
    }
    {
        double v = (double)ss;
#pragma unroll
        for (int o = 16; o > 0; o >>= 1)
            v += __shfl_down_sync(0xffffffffu, v, o);
        if (lane == 0) s_red[wid] = v;
        __syncthreads();
        if (tid == 0) {
            double t = 0.0;
#pragma unroll
            for (int w = 0; w < 8; w++) t += s_red[w];
            atomicAdd(&g_loss, t);
        }
    }
}

// ---------------------------------------------------------------------------
// Finalize: loss + perplexity.
// ---------------------------------------------------------------------------
__global__ void finalize_kernel(float* __restrict__ out) {
    __shared__ float red[32];
    const int tid = threadIdx.x;
    float p = (float)g_count[tid] * (1.0f / (float)N_INPUTS);
    float v = p * logf(p + 1e-10f);
#pragma unroll
    for (int o = 16; o > 0; o >>= 1)
        v += __shfl_down_sync(0xffffffffu, v, o);
    if ((tid & 31) == 0) red[tid >> 5] = v;
    __syncthreads();
    if (tid < 32) {
        float t = red[tid];
#pragma unroll
        for (int o = 16; o > 0; o >>= 1)
            t += __shfl_down_sync(0xffffffffu, t, o);
        if (tid == 0) {
            out[PP_OFF] = expf(-t);
            double mean = g_loss / ((double)N_INPUTS * (double)EMB_DIM);
            out[0] = (float)(0.25 * mean);
        }
    }
}

extern "C" void kernel_launch(void* const* d_in, const int* in_sizes, int n_in,
                              void* d_out, int out_size) {
    const float* inputs = (const float*)d_in[0];
    const float* emb    = (const float*)d_in[1];
    float* out = (float*)d_out;

    cudaFuncSetAttribute(vq_main_kernel,
                         cudaFuncAttributeMaxDynamicSharedMemorySize, DYN_SMEM);

    prep_kernel<<<(NUM_EMB * 8) / 256, 256>>>(emb);
    vq_main_kernel<<<N_INPUTS / M_TILE, THREADS, DYN_SMEM>>>(inputs, emb, out);
    finalize_kernel<<<1, NUM_EMB>>>(out);
}

// round 12
// speedup vs baseline: 1.5278x; 1.5278x over previous
#include <cuda_runtime.h>
#include <cuda_fp16.h>
#include <cstdint>

// VQ-VAE on GB300: fp16 3-term split mma.sync distances, FMNMX top-1 +
// slice-2nd tripwire (R10 structure, 235.9us), with PHASE_CODES halved to 64
// so dyn smem = 50.3KB -> 3 CTAs/SM. B1/B2 register lifetimes split to stay
// under the occ-3 register cap.
//
// d_out layout (fp32): [0]=loss, [1..1+N*D)=quantized, [1+N*D]=perplexity,
//                      [2+N*D ..)=encodings one-hot.

#define N_INPUTS 131072
#define EMB_DIM  64
#define NUM_EMB  1024
#define M_TILE   128
#define THREADS  256
#define PHASES   16
#define PHASE_CODES 64
#define MARGIN   0.01f

#define Q_OFF   ((size_t)1)
#define PP_OFF  ((size_t)(1 + (size_t)N_INPUTS * EMB_DIM))
#define ENC_OFF ((size_t)(2 + (size_t)N_INPUTS * EMB_DIM))

// smem layout (bytes from dynamic-smem base)
#define EPITCH      144                 // 72 halfs per code row (conflict-free)
#define EBUF_SPLIT  (PHASE_CODES * EPITCH)      // 9216
#define EBUF_SIZE   (2 * EBUF_SPLIT)            // e1 + e2 = 18432
#define SM_E        0                            // 2 buffers = 36864
#define SM_NORM     36864                        // 1024 floats
#define SM_CANDV    40960                        // 128*4 floats (slice top-1)
#define SM_CAND2    43008                        // 128*4 floats (slice 2nd val)
#define SM_CANDI    45056                        // 128*4 ints
#define SM_BIDX     47104                        // 128 ints
#define SM_RED      47616                        // 8 doubles
#define SM_QN       47680                        // int
#define SM_QROWS    47684                        // 128 ints
#define SM_XSTG     48208                        // 8 warps * 256B (16B aligned)
#define DYN_SMEM    50304

__device__ float  g_enorm[NUM_EMB];
__device__ __half g_e1[NUM_EMB * EMB_DIM];
__device__ __half g_e2[NUM_EMB * EMB_DIM];
__device__ int    g_count[NUM_EMB];
__device__ double g_loss;

__device__ __forceinline__ uint32_t s2u(const void* p) {
    uint32_t a;
    asm("{ .reg .u64 t; cvta.to.shared.u64 t, %1; cvt.u32.u64 %0, t; }"
        : "=r"(a) : "l"(p));
    return a;
}

__device__ __forceinline__ void split2(float lo, float hi,
                                       unsigned& h1, unsigned& h2) {
    __half2 a = __floats2half2_rn(lo, hi);
    float2 af = __half22float2(a);
    __half2 b = __floats2half2_rn(lo - af.x, hi - af.y);
    h1 = *reinterpret_cast<unsigned*>(&a);
    h2 = *reinterpret_cast<unsigned*>(&b);
}

#define MMA16816(C, A, b0, b1)                                                \
    asm volatile(                                                             \
        "mma.sync.aligned.m16n8k16.row.col.f32.f16.f16.f32 "                  \
        "{%0,%1,%2,%3},{%4,%5,%6,%7},{%8,%9},{%0,%1,%2,%3};"                  \
        : "+f"((C)[0]), "+f"((C)[1]), "+f"((C)[2]), "+f"((C)[3])              \
        : "r"((A)[0]), "r"((A)[1]), "r"((A)[2]), "r"((A)[3]),                 \
          "r"(b0), "r"(b1))

#define CP16(dst, src)                                                        \
    asm volatile("cp.async.ca.shared.global [%0], [%1], 16;"                  \
                 :: "r"(dst), "l"(src) : "memory")

#define STG_CS_F2(p, v)                                                       \
    asm volatile("st.global.cs.v2.f32 [%0], {%1, %2};"                        \
                 :: "l"(p), "f"((v).x), "f"((v).y) : "memory")

// top-1 + value-only 2nd, FMNMX-based (first-occurrence wins on ties:
// strict < for index update, codes visited ascending)
#define UPD(h, d, ix)                                                         \
    do {                                                                      \
        float _d = (d);                                                       \
        float _t = fmaxf(s0v[h], _d);                                         \
        s1v[h] = fminf(s1v[h], _t);                                           \
        if (_d < s0v[h]) s0i[h] = (ix);                                       \
        s0v[h] = fminf(s0v[h], _d);                                           \
    } while (0)

// ---------------------------------------------------------------------------
// Prep: norms, fp16 split of embeddings (row-major), zero accumulators.
// ---------------------------------------------------------------------------
__global__ void prep_kernel(const float* __restrict__ emb) {
    int g = blockIdx.x * blockDim.x + threadIdx.x;   // 0..8191
    int k = g >> 3, seg = g & 7;
    const float* er = emb + (size_t)k * EMB_DIM + seg * 8;
    float s = 0.0f;
#pragma unroll
    for (int i = 0; i < 8; i += 2) {
        float a = er[i], b = er[i + 1];
        s = fmaf(a, a, s);
        s = fmaf(b, b, s);
        unsigned h1, h2;
        split2(a, b, h1, h2);
        size_t o = (size_t)k * EMB_DIM + seg * 8 + i;
        *reinterpret_cast<unsigned*>(&g_e1[o]) = h1;
        *reinterpret_cast<unsigned*>(&g_e2[o]) = h2;
    }
#pragma unroll
    for (int o = 4; o > 0; o >>= 1)
        s += __shfl_down_sync(0xffffffffu, s, o, 8);
    if (seg == 0) {
        g_enorm[k] = s;
        g_count[k] = 0;
        if (k == 0) g_loss = 0.0;
    }
}

// ---------------------------------------------------------------------------
// Main kernel: CTA = 128 rows; warp w owns rows w*16..w*16+15.
// ---------------------------------------------------------------------------
__device__ __forceinline__ void prefetch_phase(uint32_t smu, int tid, int phase) {
    uint32_t dbase = smu + SM_E + (phase & 1) * EBUF_SIZE;
    const __half* s1 = g_e1 + (size_t)phase * PHASE_CODES * EMB_DIM;
    const __half* s2 = g_e2 + (size_t)phase * PHASE_CODES * EMB_DIM;
#pragma unroll
    for (int j = 0; j < 2; j++) {
        int c = tid + j * THREADS;       // 0..511 chunk id
        int code = c >> 3, sub = c & 7;
        uint32_t dst = dbase + code * EPITCH + sub * 16;
        CP16(dst, s1 + code * EMB_DIM + sub * 8);
        CP16(dst + EBUF_SPLIT, s2 + code * EMB_DIM + sub * 8);
    }
}

__global__ void __launch_bounds__(THREADS, 3)
vq_main_kernel(const float* __restrict__ inputs,
               const float* __restrict__ emb,
               float* __restrict__ out) {
    extern __shared__ char sm[];
    const uint32_t smu = s2u(sm);
    const int tid  = threadIdx.x;
    const int wid  = tid >> 5;
    const int lane = tid & 31;
    const int gid  = lane >> 2;
    const int tig  = lane & 3;
    const int row0 = blockIdx.x * M_TILE;

    if (tid == 0) *(int*)(sm + SM_QN) = 0;

    // enorm -> smem
    float* nsm = (float*)(sm + SM_NORM);
    for (int i = tid; i < NUM_EMB; i += THREADS) nsm[i] = g_enorm[i];

    // A fragments (x split), held for the whole kernel.
    unsigned X1[4][4], X2[4][4];
    {
        const float* xp  = inputs + (size_t)(row0 + wid * 16 + gid) * EMB_DIM;
        const float* xp8 = xp + 8 * EMB_DIM;
#pragma unroll
        for (int ks = 0; ks < 4; ks++) {
            int c0 = ks * 16 + 2 * tig;
            float2 v;
            v = *(const float2*)(xp  + c0);     split2(v.x, v.y, X1[ks][0], X2[ks][0]);
            v = *(const float2*)(xp8 + c0);     split2(v.x, v.y, X1[ks][1], X2[ks][1]);
            v = *(const float2*)(xp  + c0 + 8); split2(v.x, v.y, X1[ks][2], X2[ks][2]);
            v = *(const float2*)(xp8 + c0 + 8); split2(v.x, v.y, X1[ks][3], X2[ks][3]);
        }
    }

    prefetch_phase(smu, tid, 0);
    asm volatile("cp.async.commit_group;" ::: "memory");

    float s0v[2] = {3.4e38f, 3.4e38f}, s1v[2] = {3.4e38f, 3.4e38f};
    int   s0i[2] = {0, 0};

    float2* const enc = (float2*)(out + ENC_OFF);   // 8B-aligned

    for (int phase = 0; phase < PHASES; phase++) {
        if (phase + 1 < PHASES) {
            prefetch_phase(smu, tid, phase + 1);
            asm volatile("cp.async.commit_group;" ::: "memory");
            asm volatile("cp.async.wait_group 1;" ::: "memory");
        } else {
            asm volatile("cp.async.wait_group 0;" ::: "memory");
        }
        __syncthreads();

        const char* e1b = sm + SM_E + (phase & 1) * EBUF_SIZE;
        const char* e2b = e1b + EBUF_SPLIT;

        for (int it = 0; it < PHASE_CODES / 16; it++) {
            const int lc = it * 16;
            float C0[4] = {0.f, 0.f, 0.f, 0.f};
            float C1[4] = {0.f, 0.f, 0.f, 0.f};
            // ---- B1 live range: X1*B1 and X2*B1 passes ----
            {
                unsigned B1[2][4][2];
#pragma unroll
                for (int nt = 0; nt < 2; nt++) {
                    int base = (lc + nt * 8 + gid) * EPITCH + 4 * tig;
#pragma unroll
                    for (int ks = 0; ks < 4; ks++) {
                        int off = base + ks * 32;
                        B1[nt][ks][0] = *(const unsigned*)(e1b + off);
                        B1[nt][ks][1] = *(const unsigned*)(e1b + off + 16);
                    }
                }
#pragma unroll
                for (int ks = 0; ks < 4; ks++) {
                    MMA16816(C0, X1[ks], B1[0][ks][0], B1[0][ks][1]);
                    MMA16816(C1, X1[ks], B1[1][ks][0], B1[1][ks][1]);
                }
#pragma unroll
                for (int ks = 0; ks < 4; ks++) {
                    MMA16816(C0, X2[ks], B1[0][ks][0], B1[0][ks][1]);
                    MMA16816(C1, X2[ks], B1[1][ks][0], B1[1][ks][1]);
                }
            }
            // ---- B2 live range: X1*B2 pass ----
            {
                unsigned B2[2][4][2];
#pragma unroll
                for (int nt = 0; nt < 2; nt++) {
                    int base = (lc + nt * 8 + gid) * EPITCH + 4 * tig;
#pragma unroll
                    for (int ks = 0; ks < 4; ks++) {
                        int off = base + ks * 32;
                        B2[nt][ks][0] = *(const unsigned*)(e2b + off);
                        B2[nt][ks][1] = *(const unsigned*)(e2b + off + 16);
                    }
                }
#pragma unroll
                for (int ks = 0; ks < 4; ks++) {
                    MMA16816(C0, X1[ks], B2[0][ks][0], B2[0][ks][1]);
                    MMA16816(C1, X1[ks], B2[1][ks][0], B2[1][ks][1]);
                }
            }
            // dist + per-row-half top1 + value-only 2nd (codes ascending)
            const int cb = phase * PHASE_CODES + lc;
            float n0 = nsm[cb + 2 * tig],     n1 = nsm[cb + 2 * tig + 1];
            float n2 = nsm[cb + 8 + 2 * tig], n3 = nsm[cb + 9 + 2 * tig];
            UPD(0, fmaf(-2.f, C0[0], n0), cb + 2 * tig);
            UPD(0, fmaf(-2.f, C0[1], n1), cb + 2 * tig + 1);
            UPD(0, fmaf(-2.f, C1[0], n2), cb + 8 + 2 * tig);
            UPD(0, fmaf(-2.f, C1[1], n3), cb + 9 + 2 * tig);
            UPD(1, fmaf(-2.f, C0[2], n0), cb + 2 * tig);
            UPD(1, fmaf(-2.f, C0[3], n1), cb + 2 * tig + 1);
            UPD(1, fmaf(-2.f, C1[2], n2), cb + 8 + 2 * tig);
            UPD(1, fmaf(-2.f, C1[3], n3), cb + 9 + 2 * tig);
        }

        // ---- stream the one-hot ZERO slab for this phase's 64 columns ----
        {
            const float2 z = make_float2(0.0f, 0.0f);
#pragma unroll 4
            for (int i = tid; i < M_TILE * 32; i += THREADS) {
                int r = i >> 5, c2 = i & 31;
                float2* p = enc + (size_t)(row0 + r) * 512 + phase * 32 + c2;
                STG_CS_F2(p, z);
            }
        }
        __syncthreads();   // buffer reuse safety for next prefetch
    }

    // ---- publish candidates: row -> 4 (top1 val, idx) + 4 slice-2nd vals ----
    float* cv = (float*)(sm + SM_CANDV);
    float* c2 = (float*)(sm + SM_CAND2);
    int*   ci = (int*)(sm + SM_CANDI);
    {
        int r0 = wid * 16 + gid, r1 = r0 + 8;
        cv[r0 * 4 + tig] = s0v[0]; ci[r0 * 4 + tig] = s0i[0]; c2[r0 * 4 + tig] = s1v[0];
        cv[r1 * 4 + tig] = s0v[1]; ci[r1 * 4 + tig] = s0i[1]; c2[r1 * 4 + tig] = s1v[1];
    }
    __syncthreads();

    // ---- per-row: merge, tripwire, rerank or queue exact full scan ----
    int* s_bidx = (int*)(sm + SM_BIDX);
    int* q_n    = (int*)(sm + SM_QN);
    int* q_rows = (int*)(sm + SM_QROWS);
    if (tid < M_TILE) {
        const float* cvr = cv + tid * 4;
        const float* c2r = c2 + tid * 4;
        const int*   cir = ci + tid * 4;
        float m0 = 3.4e38f; int mi = 0x7fffffff;
#pragma unroll
        for (int s = 0; s < 4; s++) {
            float v = cvr[s]; int id = cir[s];
            if (v < m0 || (v == m0 && id < mi)) { m0 = v; mi = id; }
        }
        const float lim = m0 + MARGIN;
        float h2 = fminf(fminf(c2r[0], c2r[1]), fminf(c2r[2], c2r[3]));
        if (h2 <= lim) {
            // a hidden slice-2nd may be in-margin: exact full scan needed
            q_rows[atomicAdd(q_n, 1)] = tid;
        } else {
            int cnt = 0;
#pragma unroll
            for (int s = 0; s < 4; s++) cnt += (cvr[s] <= lim);
            int bidx = mi;
            if (cnt > 1) {               // exact fp32 rerank among published
                const float* xr = inputs + (size_t)(row0 + tid) * EMB_DIM;
                float bd = 3.4e38f; int bb = 0x7fffffff;
#pragma unroll 1
                for (int s = 0; s < 4; s++) {
                    if (cvr[s] <= lim) {
                        int id = cir[s];
                        const float4* er = (const float4*)(emb + (size_t)id * EMB_DIM);
                        float dot = 0.f;
#pragma unroll
                        for (int i = 0; i < EMB_DIM / 4; i++) {
                            float4 e = __ldg(er + i);
                            float4 x = *(const float4*)(xr + 4 * i);
                            dot = fmaf(x.x, e.x, dot); dot = fmaf(x.y, e.y, dot);
                            dot = fmaf(x.z, e.z, dot); dot = fmaf(x.w, e.w, dot);
                        }
                        float d = fmaf(-2.f, dot, nsm[id]);
                        if (d < bd || (d == bd && id < bb)) { bd = d; bb = id; }
                    }
                }
                bidx = bb;
            }
            s_bidx[tid] = bidx;
            atomicAdd(&g_count[bidx], 1);
            out[ENC_OFF + (size_t)(row0 + tid) * NUM_EMB + bidx] = 1.0f;
        }
    }
    __syncthreads();

    // ---- exact full scan for queued rows (one warp per row; rare) ----
    {
        const int nq = *q_n;
        float4* xs = (float4*)(sm + SM_XSTG + wid * 256);
        for (int qi = wid; qi < nq; qi += 8) {
            const int r = q_rows[qi];
            {
                const float2 v = *(const float2*)
                    (inputs + (size_t)(row0 + r) * EMB_DIM + 2 * lane);
                ((float2*)xs)[lane] = v;
            }
            __syncwarp();
            float bd = 3.4e38f; int bi = 0x7fffffff;
            for (int c = lane; c < NUM_EMB; c += 32) {
                const float4* er = (const float4*)(emb + (size_t)c * EMB_DIM);
                float dot = 0.f;
#pragma unroll
                for (int i = 0; i < EMB_DIM / 4; i++) {
                    float4 e = __ldg(er + i);
                    float4 x = xs[i];
                    dot = fmaf(x.x, e.x, dot); dot = fmaf(x.y, e.y, dot);
                    dot = fmaf(x.z, e.z, dot); dot = fmaf(x.w, e.w, dot);
                }
                float d = fmaf(-2.f, dot, nsm[c]);
                if (d < bd || (d == bd && c < bi)) { bd = d; bi = c; }
            }
#pragma unroll
            for (int o = 16; o > 0; o >>= 1) {
                float od = __shfl_down_sync(0xffffffffu, bd, o);
                int   oi = __shfl_down_sync(0xffffffffu, bi, o);
                if (od < bd || (od == bd && oi < bi)) { bd = od; bi = oi; }
            }
            bi = __shfl_sync(0xffffffffu, bi, 0);
            if (lane == 0) {
                s_bidx[r] = bi;
                atomicAdd(&g_count[bi], 1);
                out[ENC_OFF + (size_t)(row0 + r) * NUM_EMB + bi] = 1.0f;
            }
            __syncwarp();
        }
    }
    __syncthreads();

    // ---- quantized + commitment loss ----
    double* s_red = (double*)(sm + SM_RED);
    float ss = 0.0f;
    for (int i = tid; i < M_TILE * EMB_DIM; i += THREADS) {
        int r = i >> 6, cl = i & 63;
        float x = inputs[(size_t)(row0 + r) * EMB_DIM + cl];
        float e = emb[(size_t)s_bidx[r] * EMB_DIM + cl];
        float d = e - x;
        out[Q_OFF + (size_t)(row0 + r) * EMB_DIM + cl] = x + d;
        ss = fmaf(d, d, ss);
    }
    {
        double v = (double)ss;
#pragma unroll
        for (int o = 16; o > 0; o >>= 1)
            v += __shfl_down_sync(0xffffffffu, v, o);
        if (lane == 0) s_red[wid] = v;
        __syncthreads();
        if (tid == 0) {
            double t = 0.0;
#pragma unroll
            for (int w = 0; w < 8; w++) t += s_red[w];
            atomicAdd(&g_loss, t);
        }
    }
}

// ---------------------------------------------------------------------------
// Finalize: loss + perplexity.
// ---------------------------------------------------------------------------
__global__ void finalize_kernel(float* __restrict__ out) {
    __shared__ float red[32];
    const int tid = threadIdx.x;
    float p = (float)g_count[tid] * (1.0f / (float)N_INPUTS);
    float v = p * logf(p + 1e-10f);
#pragma unroll
    for (int o = 16; o > 0; o >>= 1)
        v += __shfl_down_sync(0xffffffffu, v, o);
    if ((tid & 31) == 0) red[tid >> 5] = v;
    __syncthreads();
    if (tid < 32) {
        float t = red[tid];
#pragma unroll
        for (int o = 16; o > 0; o >>= 1)
            t += __shfl_down_sync(0xffffffffu, t, o);
        if (tid == 0) {
            out[PP_OFF] = expf(-t);
            double mean = g_loss / ((double)N_INPUTS * (double)EMB_DIM);
            out[0] = (float)(0.25 * mean);
        }
    }
}

extern "C" void kernel_launch(void* const* d_in, const int* in_sizes, int n_in,
                              void* d_out, int out_size) {
    const float* inputs = (const float*)d_in[0];
    const float* emb    = (const float*)d_in[1];
    float* out = (float*)d_out;

    cudaFuncSetAttribute(vq_main_kernel,
                         cudaFuncAttributeMaxDynamicSharedMemorySize, DYN_SMEM);

    prep_kernel<<<(NUM_EMB * 8) / 256, 256>>>(emb);
    vq_main_kernel<<<N_INPUTS / M_TILE, THREADS, DYN_SMEM>>>(inputs, emb, out);
    finalize_kernel<<<1, NUM_EMB>>>(out);
}

// round 13
// speedup vs baseline: 1.5538x; 1.0170x over previous
#include <cuda_runtime.h>
#include <cuda_fp16.h>
#include <cstdint>

// VQ-VAE on GB300: fp16 3-term split mma.sync distances, FMNMX top-1 +
// slice-2nd tripwire, occ-3 (R12, 222us). R13: MARGIN 0.002 (still >=2x the
// provable approx-error bound) + finalize folded into main via last-CTA.
//
// d_out layout (fp32): [0]=loss, [1..1+N*D)=quantized, [1+N*D]=perplexity,
//                      [2+N*D ..)=encodings one-hot.

#define N_INPUTS 131072
#define EMB_DIM  64
#define NUM_EMB  1024
#define M_TILE   128
#define THREADS  256
#define PHASES   16
#define PHASE_CODES 64
#define MARGIN   0.002f

#define Q_OFF   ((size_t)1)
#define PP_OFF  ((size_t)(1 + (size_t)N_INPUTS * EMB_DIM))
#define ENC_OFF ((size_t)(2 + (size_t)N_INPUTS * EMB_DIM))

// smem layout (bytes from dynamic-smem base)
#define EPITCH      144                 // 72 halfs per code row (conflict-free)
#define EBUF_SPLIT  (PHASE_CODES * EPITCH)      // 9216
#define EBUF_SIZE   (2 * EBUF_SPLIT)            // e1 + e2 = 18432
#define SM_E        0                            // 2 buffers = 36864
#define SM_NORM     36864                        // 1024 floats
#define SM_CANDV    40960                        // 128*4 floats (slice top-1)
#define SM_CAND2    43008                        // 128*4 floats (slice 2nd val)
#define SM_CANDI    45056                        // 128*4 ints
#define SM_BIDX     47104                        // 128 ints
#define SM_RED      47616                        // 8 doubles
#define SM_QN       47680                        // int
#define SM_QROWS    47684                        // 128 ints
#define SM_XSTG     48208                        // 8 warps * 256B (16B aligned)
#define SM_LAST     50256                        // int (last-CTA flag)
#define SM_FRED     50260                        // 8 floats (finalize reduce)
#define DYN_SMEM    50304

__device__ float    g_enorm[NUM_EMB];
__device__ __half   g_e1[NUM_EMB * EMB_DIM];
__device__ __half   g_e2[NUM_EMB * EMB_DIM];
__device__ int      g_count[NUM_EMB];
__device__ double   g_loss;
__device__ unsigned g_done;

__device__ __forceinline__ uint32_t s2u(const void* p) {
    uint32_t a;
    asm("{ .reg .u64 t; cvta.to.shared.u64 t, %1; cvt.u32.u64 %0, t; }"
        : "=r"(a) : "l"(p));
    return a;
}

__device__ __forceinline__ void split2(float lo, float hi,
                                       unsigned& h1, unsigned& h2) {
    __half2 a = __floats2half2_rn(lo, hi);
    float2 af = __half22float2(a);
    __half2 b = __floats2half2_rn(lo - af.x, hi - af.y);
    h1 = *reinterpret_cast<unsigned*>(&a);
    h2 = *reinterpret_cast<unsigned*>(&b);
}

#define MMA16816(C, A, b0, b1)                                                \
    asm volatile(                                                             \
        "mma.sync.aligned.m16n8k16.row.col.f32.f16.f16.f32 "                  \
        "{%0,%1,%2,%3},{%4,%5,%6,%7},{%8,%9},{%0,%1,%2,%3};"                  \
        : "+f"((C)[0]), "+f"((C)[1]), "+f"((C)[2]), "+f"((C)[3])              \
        : "r"((A)[0]), "r"((A)[1]), "r"((A)[2]), "r"((A)[3]),                 \
          "r"(b0), "r"(b1))

#define CP16(dst, src)                                                        \
    asm volatile("cp.async.ca.shared.global [%0], [%1], 16;"                  \
                 :: "r"(dst), "l"(src) : "memory")

#define STG_CS_F2(p, v)                                                       \
    asm volatile("st.global.cs.v2.f32 [%0], {%1, %2};"                        \
                 :: "l"(p), "f"((v).x), "f"((v).y) : "memory")

// top-1 + value-only 2nd, FMNMX-based (first-occurrence wins on ties:
// strict < for index update, codes visited ascending)
#define UPD(h, d, ix)                                                         \
    do {                                                                      \
        float _d = (d);                                                       \
        float _t = fmaxf(s0v[h], _d);                                         \
        s1v[h] = fminf(s1v[h], _t);                                           \
        if (_d < s0v[h]) s0i[h] = (ix);                                       \
        s0v[h] = fminf(s0v[h], _d);                                           \
    } while (0)

// ---------------------------------------------------------------------------
// Prep: norms, fp16 split of embeddings (row-major), zero accumulators.
// ---------------------------------------------------------------------------
__global__ void prep_kernel(const float* __restrict__ emb) {
    int g = blockIdx.x * blockDim.x + threadIdx.x;   // 0..8191
    int k = g >> 3, seg = g & 7;
    const float* er = emb + (size_t)k * EMB_DIM + seg * 8;
    float s = 0.0f;
#pragma unroll
    for (int i = 0; i < 8; i += 2) {
        float a = er[i], b = er[i + 1];
        s = fmaf(a, a, s);
        s = fmaf(b, b, s);
        unsigned h1, h2;
        split2(a, b, h1, h2);
        size_t o = (size_t)k * EMB_DIM + seg * 8 + i;
        *reinterpret_cast<unsigned*>(&g_e1[o]) = h1;
        *reinterpret_cast<unsigned*>(&g_e2[o]) = h2;
    }
#pragma unroll
    for (int o = 4; o > 0; o >>= 1)
        s += __shfl_down_sync(0xffffffffu, s, o, 8);
    if (seg == 0) {
        g_enorm[k] = s;
        g_count[k] = 0;
        if (k == 0) { g_loss = 0.0; g_done = 0u; }
    }
}

// ---------------------------------------------------------------------------
// Main kernel: CTA = 128 rows; warp w owns rows w*16..w*16+15.
// ---------------------------------------------------------------------------
__device__ __forceinline__ void prefetch_phase(uint32_t smu, int tid, int phase) {
    uint32_t dbase = smu + SM_E + (phase & 1) * EBUF_SIZE;
    const __half* s1 = g_e1 + (size_t)phase * PHASE_CODES * EMB_DIM;
    const __half* s2 = g_e2 + (size_t)phase * PHASE_CODES * EMB_DIM;
#pragma unroll
    for (int j = 0; j < 2; j++) {
        int c = tid + j * THREADS;       // 0..511 chunk id
        int code = c >> 3, sub = c & 7;
        uint32_t dst = dbase + code * EPITCH + sub * 16;
        CP16(dst, s1 + code * EMB_DIM + sub * 8);
        CP16(dst + EBUF_SPLIT, s2 + code * EMB_DIM + sub * 8);
    }
}

__global__ void __launch_bounds__(THREADS, 3)
vq_main_kernel(const float* __restrict__ inputs,
               const float* __restrict__ emb,
               float* __restrict__ out) {
    extern __shared__ char sm[];
    const uint32_t smu = s2u(sm);
    const int tid  = threadIdx.x;
    const int wid  = tid >> 5;
    const int lane = tid & 31;
    const int gid  = lane >> 2;
    const int tig  = lane & 3;
    const int row0 = blockIdx.x * M_TILE;

    if (tid == 0) *(int*)(sm + SM_QN) = 0;

    // enorm -> smem
    float* nsm = (float*)(sm + SM_NORM);
    for (int i = tid; i < NUM_EMB; i += THREADS) nsm[i] = g_enorm[i];

    // A fragments (x split), held for the whole kernel.
    unsigned X1[4][4], X2[4][4];
    {
        const float* xp  = inputs + (size_t)(row0 + wid * 16 + gid) * EMB_DIM;
        const float* xp8 = xp + 8 * EMB_DIM;
#pragma unroll
        for (int ks = 0; ks < 4; ks++) {
            int c0 = ks * 16 + 2 * tig;
            float2 v;
            v = *(const float2*)(xp  + c0);     split2(v.x, v.y, X1[ks][0], X2[ks][0]);
            v = *(const float2*)(xp8 + c0);     split2(v.x, v.y, X1[ks][1], X2[ks][1]);
            v = *(const float2*)(xp  + c0 + 8); split2(v.x, v.y, X1[ks][2], X2[ks][2]);
            v = *(const float2*)(xp8 + c0 + 8); split2(v.x, v.y, X1[ks][3], X2[ks][3]);
        }
    }

    prefetch_phase(smu, tid, 0);
    asm volatile("cp.async.commit_group;" ::: "memory");

    float s0v[2] = {3.4e38f, 3.4e38f}, s1v[2] = {3.4e38f, 3.4e38f};
    int   s0i[2] = {0, 0};

    float2* const enc = (float2*)(out + ENC_OFF);   // 8B-aligned

    for (int phase = 0; phase < PHASES; phase++) {
        if (phase + 1 < PHASES) {
            prefetch_phase(smu, tid, phase + 1);
            asm volatile("cp.async.commit_group;" ::: "memory");
            asm volatile("cp.async.wait_group 1;" ::: "memory");
        } else {
            asm volatile("cp.async.wait_group 0;" ::: "memory");
        }
        __syncthreads();

        const char* e1b = sm + SM_E + (phase & 1) * EBUF_SIZE;
        const char* e2b = e1b + EBUF_SPLIT;

        for (int it = 0; it < PHASE_CODES / 16; it++) {
            const int lc = it * 16;
            float C0[4] = {0.f, 0.f, 0.f, 0.f};
            float C1[4] = {0.f, 0.f, 0.f, 0.f};
            // ---- B1 live range: X1*B1 and X2*B1 passes ----
            {
                unsigned B1[2][4][2];
#pragma unroll
                for (int nt = 0; nt < 2; nt++) {
                    int base = (lc + nt * 8 + gid) * EPITCH + 4 * tig;
#pragma unroll
                    for (int ks = 0; ks < 4; ks++) {
                        int off = base + ks * 32;
                        B1[nt][ks][0] = *(const unsigned*)(e1b + off);
                        B1[nt][ks][1] = *(const unsigned*)(e1b + off + 16);
                    }
                }
#pragma unroll
                for (int ks = 0; ks < 4; ks++) {
                    MMA16816(C0, X1[ks], B1[0][ks][0], B1[0][ks][1]);
                    MMA16816(C1, X1[ks], B1[1][ks][0], B1[1][ks][1]);
                }
#pragma unroll
                for (int ks = 0; ks < 4; ks++) {
                    MMA16816(C0, X2[ks], B1[0][ks][0], B1[0][ks][1]);
                    MMA16816(C1, X2[ks], B1[1][ks][0], B1[1][ks][1]);
                }
            }
            // ---- B2 live range: X1*B2 pass ----
            {
                unsigned B2[2][4][2];
#pragma unroll
                for (int nt = 0; nt < 2; nt++) {
                    int base = (lc + nt * 8 + gid) * EPITCH + 4 * tig;
#pragma unroll
                    for (int ks = 0; ks < 4; ks++) {
                        int off = base + ks * 32;
                        B2[nt][ks][0] = *(const unsigned*)(e2b + off);
                        B2[nt][ks][1] = *(const unsigned*)(e2b + off + 16);
                    }
                }
#pragma unroll
                for (int ks = 0; ks < 4; ks++) {
                    MMA16816(C0, X1[ks], B2[0][ks][0], B2[0][ks][1]);
                    MMA16816(C1, X1[ks], B2[1][ks][0], B2[1][ks][1]);
                }
            }
            // dist + per-row-half top1 + value-only 2nd (codes ascending)
            const int cb = phase * PHASE_CODES + lc;
            float n0 = nsm[cb + 2 * tig],     n1 = nsm[cb + 2 * tig + 1];
            float n2 = nsm[cb + 8 + 2 * tig], n3 = nsm[cb + 9 + 2 * tig];
            UPD(0, fmaf(-2.f, C0[0], n0), cb + 2 * tig);
            UPD(0, fmaf(-2.f, C0[1], n1), cb + 2 * tig + 1);
            UPD(0, fmaf(-2.f, C1[0], n2), cb + 8 + 2 * tig);
            UPD(0, fmaf(-2.f, C1[1], n3), cb + 9 + 2 * tig);
            UPD(1, fmaf(-2.f, C0[2], n0), cb + 2 * tig);
            UPD(1, fmaf(-2.f, C0[3], n1), cb + 2 * tig + 1);
            UPD(1, fmaf(-2.f, C1[2], n2), cb + 8 + 2 * tig);
            UPD(1, fmaf(-2.f, C1[3], n3), cb + 9 + 2 * tig);
        }

        // ---- stream the one-hot ZERO slab for this phase's 64 columns ----
        {
            const float2 z = make_float2(0.0f, 0.0f);
#pragma unroll 4
            for (int i = tid; i < M_TILE * 32; i += THREADS) {
                int r = i >> 5, c2 = i & 31;
                float2* p = enc + (size_t)(row0 + r) * 512 + phase * 32 + c2;
                STG_CS_F2(p, z);
            }
        }
        __syncthreads();   // buffer reuse safety for next prefetch
    }

    // ---- publish candidates: row -> 4 (top1 val, idx) + 4 slice-2nd vals ----
    float* cv = (float*)(sm + SM_CANDV);
    float* c2 = (float*)(sm + SM_CAND2);
    int*   ci = (int*)(sm + SM_CANDI);
    {
        int r0 = wid * 16 + gid, r1 = r0 + 8;
        cv[r0 * 4 + tig] = s0v[0]; ci[r0 * 4 + tig] = s0i[0]; c2[r0 * 4 + tig] = s1v[0];
        cv[r1 * 4 + tig] = s0v[1]; ci[r1 * 4 + tig] = s0i[1]; c2[r1 * 4 + tig] = s1v[1];
    }
    __syncthreads();

    // ---- per-row: merge, tripwire, rerank or queue exact full scan ----
    int* s_bidx = (int*)(sm + SM_BIDX);
    int* q_n    = (int*)(sm + SM_QN);
    int* q_rows = (int*)(sm + SM_QROWS);
    if (tid < M_TILE) {
        const float* cvr = cv + tid * 4;
        const float* c2r = c2 + tid * 4;
        const int*   cir = ci + tid * 4;
        float m0 = 3.4e38f; int mi = 0x7fffffff;
#pragma unroll
        for (int s = 0; s < 4; s++) {
            float v = cvr[s]; int id = cir[s];
            if (v < m0 || (v == m0 && id < mi)) { m0 = v; mi = id; }
        }
        const float lim = m0 + MARGIN;
        float h2 = fminf(fminf(c2r[0], c2r[1]), fminf(c2r[2], c2r[3]));
        if (h2 <= lim) {
            // a hidden slice-2nd may be in-margin: exact full scan needed
            q_rows[atomicAdd(q_n, 1)] = tid;
        } else {
            int cnt = 0;
#pragma unroll
            for (int s = 0; s < 4; s++) cnt += (cvr[s] <= lim);
            int bidx = mi;
            if (cnt > 1) {               // exact fp32 rerank among published
                const float* xr = inputs + (size_t)(row0 + tid) * EMB_DIM;
                float bd = 3.4e38f; int bb = 0x7fffffff;
#pragma unroll 1
                for (int s = 0; s < 4; s++) {
                    if (cvr[s] <= lim) {
                        int id = cir[s];
                        const float4* er = (const float4*)(emb + (size_t)id * EMB_DIM);
                        float dot = 0.f;
#pragma unroll
                        for (int i = 0; i < EMB_DIM / 4; i++) {
                            float4 e = __ldg(er + i);
                            float4 x = *(const float4*)(xr + 4 * i);
                            dot = fmaf(x.x, e.x, dot); dot = fmaf(x.y, e.y, dot);
                            dot = fmaf(x.z, e.z, dot); dot = fmaf(x.w, e.w, dot);
                        }
                        float d = fmaf(-2.f, dot, nsm[id]);
                        if (d < bd || (d == bd && id < bb)) { bd = d; bb = id; }
                    }
                }
                bidx = bb;
            }
            s_bidx[tid] = bidx;
            atomicAdd(&g_count[bidx], 1);
            out[ENC_OFF + (size_t)(row0 + tid) * NUM_EMB + bidx] = 1.0f;
        }
    }
    __syncthreads();

    // ---- exact full scan for queued rows (one warp per row; rare) ----
    {
        const int nq = *q_n;
        float4* xs = (float4*)(sm + SM_XSTG + wid * 256);
        for (int qi = wid; qi < nq; qi += 8) {
            const int r = q_rows[qi];
            {
                const float2 v = *(const float2*)
                    (inputs + (size_t)(row0 + r) * EMB_DIM + 2 * lane);
                ((float2*)xs)[lane] = v;
            }
            __syncwarp();
            float bd = 3.4e38f; int bi = 0x7fffffff;
            for (int c = lane; c < NUM_EMB; c += 32) {
                const float4* er = (const float4*)(emb + (size_t)c * EMB_DIM);
                float dot = 0.f;
#pragma unroll
                for (int i = 0; i < EMB_DIM / 4; i++) {
                    float4 e = __ldg(er + i);
                    float4 x = xs[i];
                    dot = fmaf(x.x, e.x, dot); dot = fmaf(x.y, e.y, dot);
                    dot = fmaf(x.z, e.z, dot); dot = fmaf(x.w, e.w, dot);
                }
                float d = fmaf(-2.f, dot, nsm[c]);
                if (d < bd || (d == bd && c < bi)) { bd = d; bi = c; }
            }
#pragma unroll
            for (int o = 16; o > 0; o >>= 1) {
                float od = __shfl_down_sync(0xffffffffu, bd, o);
                int   oi = __shfl_down_sync(0xffffffffu, bi, o);
                if (od < bd || (od == bd && oi < bi)) { bd = od; bi = oi; }
            }
            bi = __shfl_sync(0xffffffffu, bi, 0);
            if (lane == 0) {
                s_bidx[r] = bi;
                atomicAdd(&g_count[bi], 1);
                out[ENC_OFF + (size_t)(row0 + r) * NUM_EMB + bi] = 1.0f;
            }
            __syncwarp();
        }
    }
    __syncthreads();

    // ---- quantized + commitment loss ----
    double* s_red = (double*)(sm + SM_RED);
    float ss = 0.0f;
    for (int i = tid; i < M_TILE * EMB_DIM; i += THREADS) {
        int r = i >> 6, cl = i & 63;
        float x = inputs[(size_t)(row0 + r) * EMB_DIM + cl];
        float e = emb[(size_t)s_bidx[r] * EMB_DIM + cl];
        float d = e - x;
        out[Q_OFF + (size_t)(row0 + r) * EMB_DIM + cl] = x + d;
        ss = fmaf(d, d, ss);
    }
    {
        double v = (double)ss;
#pragma unroll
        for (int o = 16; o > 0; o >>= 1)
            v += __shfl_down_sync(0xffffffffu, v, o);
        if (lane == 0) s_red[wid] = v;
        __syncthreads();
        if (tid == 0) {
            double t = 0.0;
#pragma unroll
            for (int w = 0; w < 8; w++) t += s_red[w];
            atomicAdd(&g_loss, t);
        }
    }

    // ---- last CTA finalizes loss + perplexity (replaces finalize kernel) ----
    {
        int* lastf = (int*)(sm + SM_LAST);
        if (tid == 0) {
            __threadfence();
            unsigned prev = atomicAdd(&g_done, 1u);
            *lastf = (prev == (unsigned)(gridDim.x - 1)) ? 1 : 0;
        }
        __syncthreads();
        if (*lastf) {
            __threadfence();             // acquire: see all CTAs' atomics
            float* fred = (float*)(sm + SM_FRED);
            float v = 0.0f;
#pragma unroll
            for (int k = tid; k < NUM_EMB; k += THREADS) {
                float p = (float)g_count[k] * (1.0f / (float)N_INPUTS);
                v += p * logf(p + 1e-10f);
            }
#pragma unroll
            for (int o = 16; o > 0; o >>= 1)
                v += __shfl_down_sync(0xffffffffu, v, o);
            if (lane == 0) fred[wid] = v;
            __syncthreads();
            if (tid == 0) {
                float t = 0.0f;
#pragma unroll
                for (int w = 0; w < 8; w++) t += fred[w];
                out[PP_OFF] = expf(-t);
                double mean = g_loss / ((double)N_INPUTS * (double)EMB_DIM);
                out[0] = (float)(0.25 * mean);
            }
        }
    }
}

extern "C" void kernel_launch(void* const* d_in, const int* in_sizes, int n_in,
                              void* d_out, int out_size) {
    const float* inputs = (const float*)d_in[0];
    const float* emb    = (const float*)d_in[1];
    float* out = (float*)d_out;

    cudaFuncSetAttribute(vq_main_kernel,
                         cudaFuncAttributeMaxDynamicSharedMemorySize, DYN_SMEM);

    prep_kernel<<<(NUM_EMB * 8) / 256, 256>>>(emb);
    vq_main_kernel<<<N_INPUTS / M_TILE, THREADS, DYN_SMEM>>>(inputs, emb, out);
}